// round 5
// baseline (speedup 1.0000x reference)
#include <cuda_runtime.h>
#include <math.h>

// Problem constants
#define BATCH 2048
#define SEQT  80
#define EMBD  100
#define NUNITS 512

// GEMM tiling: 64x64 block tile, K-tile 16, 4x4 per thread, 256 threads.
#define BM 64
#define BN 64
#define BK 16
#define TM 4
#define TN 4
#define NTHREADS 256

// Scratch: sequence activations, ping-pong between "xproj" and "hidden seq".
// __device__ globals are the sanctioned scratch mechanism (no cudaMalloc allowed).
__device__ float g_x[(size_t)BATCH * SEQT * NUNITS]; // input-projection per (b,t)
__device__ float g_s[(size_t)BATCH * SEQT * NUNITS]; // hidden states per (b,t)

// ---------------------------------------------------------------------------
// Generic fp32 tiled GEMM: C[M,512] = A[M,512] @ W[512,512] + bias
// A, C contiguous row-major with row stride 512. M multiple of 64.
// ---------------------------------------------------------------------------
__global__ __launch_bounds__(NTHREADS) void proj_kernel(
    const float* __restrict__ A,
    const float* __restrict__ W,
    const float* __restrict__ bias,
    float* __restrict__ C)
{
    __shared__ float As[BK][BM];
    __shared__ float Bs[BK][BN];
    const int tid = threadIdx.x;
    const int tx = tid & 15, ty = tid >> 4;
    const int rowBase = blockIdx.y * BM;
    const int colBase = blockIdx.x * BN;

    // load mapping
    const int a_r = tid >> 2;           // 0..63
    const int a_k = (tid & 3) << 2;     // 0,4,8,12
    const int b_k = tid >> 4;           // 0..15
    const int b_c = (tid & 15) << 2;    // 0..60

    float acc[TM][TN] = {};

    for (int kk = 0; kk < NUNITS; kk += BK) {
        float4 av = *(const float4*)&A[(size_t)(rowBase + a_r) * NUNITS + kk + a_k];
        As[a_k + 0][a_r] = av.x; As[a_k + 1][a_r] = av.y;
        As[a_k + 2][a_r] = av.z; As[a_k + 3][a_r] = av.w;
        float4 bv = *(const float4*)&W[(size_t)(kk + b_k) * NUNITS + colBase + b_c];
        *(float4*)&Bs[b_k][b_c] = bv;
        __syncthreads();
        #pragma unroll
        for (int k = 0; k < BK; k++) {
            float4 a4 = *(const float4*)&As[k][ty * TM];
            float4 b4 = *(const float4*)&Bs[k][tx * TN];
            float ar[TM] = {a4.x, a4.y, a4.z, a4.w};
            float br[TN] = {b4.x, b4.y, b4.z, b4.w};
            #pragma unroll
            for (int i = 0; i < TM; i++)
                #pragma unroll
                for (int j = 0; j < TN; j++)
                    acc[i][j] = fmaf(ar[i], br[j], acc[i][j]);
        }
        __syncthreads();
    }

    #pragma unroll
    for (int i = 0; i < TM; i++) {
        const int r = rowBase + ty * TM + i;
        #pragma unroll
        for (int j = 0; j < TN; j++) {
            const int c = colBase + tx * TN + j;
            C[(size_t)r * NUNITS + c] = acc[i][j] + bias[c];
        }
    }
}

// ---------------------------------------------------------------------------
// Layer-1 input projection with fused embedding gather:
// C[m, n] = emb[tokens[m]] (len 100) @ W1[100,512] + b1
// ---------------------------------------------------------------------------
__global__ __launch_bounds__(NTHREADS) void embed_proj_kernel(
    const int*   __restrict__ tokens,
    const float* __restrict__ emb,
    const float* __restrict__ W,
    const float* __restrict__ bias,
    float* __restrict__ C)
{
    __shared__ float As[BK][BM];
    __shared__ float Bs[BK][BN];
    const int tid = threadIdx.x;
    const int tx = tid & 15, ty = tid >> 4;
    const int rowBase = blockIdx.y * BM;
    const int colBase = blockIdx.x * BN;

    const int a_r = tid >> 2;
    const int a_k = (tid & 3) << 2;
    const int b_k = tid >> 4;
    const int b_c = (tid & 15) << 2;

    const int tok = tokens[rowBase + a_r];   // 4 threads per row load same token (L1 hit)

    float acc[TM][TN] = {};

    for (int kk = 0; kk < EMBD; kk += BK) {
        float4 av = make_float4(0.f, 0.f, 0.f, 0.f);
        if (kk + a_k + 4 <= EMBD)   // EMBD=100, offsets multiple of 4 -> never partial
            av = *(const float4*)&emb[(size_t)tok * EMBD + kk + a_k];
        As[a_k + 0][a_r] = av.x; As[a_k + 1][a_r] = av.y;
        As[a_k + 2][a_r] = av.z; As[a_k + 3][a_r] = av.w;

        float4 bv = make_float4(0.f, 0.f, 0.f, 0.f);
        if (kk + b_k < EMBD)
            bv = *(const float4*)&W[(size_t)(kk + b_k) * NUNITS + colBase + b_c];
        *(float4*)&Bs[b_k][b_c] = bv;
        __syncthreads();
        #pragma unroll
        for (int k = 0; k < BK; k++) {
            float4 a4 = *(const float4*)&As[k][ty * TM];
            float4 b4 = *(const float4*)&Bs[k][tx * TN];
            float ar[TM] = {a4.x, a4.y, a4.z, a4.w};
            float br[TN] = {b4.x, b4.y, b4.z, b4.w};
            #pragma unroll
            for (int i = 0; i < TM; i++)
                #pragma unroll
                for (int j = 0; j < TN; j++)
                    acc[i][j] = fmaf(ar[i], br[j], acc[i][j]);
        }
        __syncthreads();
    }

    #pragma unroll
    for (int i = 0; i < TM; i++) {
        const int r = rowBase + ty * TM + i;
        #pragma unroll
        for (int j = 0; j < TN; j++) {
            const int c = colBase + tx * TN + j;
            C[(size_t)r * NUNITS + c] = acc[i][j] + bias[c];
        }
    }
}

// ---------------------------------------------------------------------------
// One recurrence step (one layer, one t):
//   C[m,:] = tanh(X[m,:] + Aprev[m,:] @ U)      m in [0, BATCH)
// A, X, C rows live inside the [B, T, H] sequence buffers -> row stride T*H.
// has_prev == 0 means h_{-1} = 0 (skip the GEMM).
// ---------------------------------------------------------------------------
__global__ __launch_bounds__(NTHREADS) void step_kernel(
    const float* __restrict__ Aprev,
    const float* __restrict__ U,
    const float* __restrict__ X,
    float* __restrict__ C,
    int has_prev)
{
    __shared__ float As[BK][BM];
    __shared__ float Bs[BK][BN];
    const size_t RSTR = (size_t)SEQT * NUNITS;   // row stride between batch rows
    const int tid = threadIdx.x;
    const int tx = tid & 15, ty = tid >> 4;
    const int rowBase = blockIdx.y * BM;
    const int colBase = blockIdx.x * BN;

    const int a_r = tid >> 2;
    const int a_k = (tid & 3) << 2;
    const int b_k = tid >> 4;
    const int b_c = (tid & 15) << 2;

    float acc[TM][TN] = {};

    if (has_prev) {
        for (int kk = 0; kk < NUNITS; kk += BK) {
            float4 av = *(const float4*)&Aprev[(size_t)(rowBase + a_r) * RSTR + kk + a_k];
            As[a_k + 0][a_r] = av.x; As[a_k + 1][a_r] = av.y;
            As[a_k + 2][a_r] = av.z; As[a_k + 3][a_r] = av.w;
            float4 bv = *(const float4*)&U[(size_t)(kk + b_k) * NUNITS + colBase + b_c];
            *(float4*)&Bs[b_k][b_c] = bv;
            __syncthreads();
            #pragma unroll
            for (int k = 0; k < BK; k++) {
                float4 a4 = *(const float4*)&As[k][ty * TM];
                float4 b4 = *(const float4*)&Bs[k][tx * TN];
                float ar[TM] = {a4.x, a4.y, a4.z, a4.w};
                float br[TN] = {b4.x, b4.y, b4.z, b4.w};
                #pragma unroll
                for (int i = 0; i < TM; i++)
                    #pragma unroll
                    for (int j = 0; j < TN; j++)
                        acc[i][j] = fmaf(ar[i], br[j], acc[i][j]);
            }
            __syncthreads();
        }
    }

    #pragma unroll
    for (int i = 0; i < TM; i++) {
        const int r = rowBase + ty * TM + i;
        #pragma unroll
        for (int j = 0; j < TN; j++) {
            const int c = colBase + tx * TN + j;
            const float v = acc[i][j] + X[(size_t)r * RSTR + c];
            C[(size_t)r * RSTR + c] = tanhf(v);
        }
    }
}

// ---------------------------------------------------------------------------
// Head: out[m] = sigmoid(dot(h_T[m,:], Wo) + bo).  One warp per row.
// ---------------------------------------------------------------------------
__global__ __launch_bounds__(256) void head_kernel(
    const float* __restrict__ S,     // g_s: [B, T, H]
    const float* __restrict__ Wo,    // [H]
    const float* __restrict__ bo,    // [1]
    float* __restrict__ out)         // [B]
{
    const int m = blockIdx.x * 8 + (threadIdx.x >> 5);
    const int lane = threadIdx.x & 31;
    const float* h = S + ((size_t)m * SEQT + (SEQT - 1)) * NUNITS;
    float s = 0.f;
    #pragma unroll 4
    for (int k = lane; k < NUNITS; k += 32)
        s = fmaf(h[k], Wo[k], s);
    #pragma unroll
    for (int o = 16; o > 0; o >>= 1)
        s += __shfl_xor_sync(0xFFFFFFFFu, s, o);
    if (lane == 0)
        out[m] = 1.f / (1.f + expf(-(s + bo[0])));
}

// ---------------------------------------------------------------------------
// Launch: embed+proj1 -> 80 steps -> [proj_l -> 80 steps] x3 -> head
// 325 graph-captured kernel launches, all on the default stream.
// ---------------------------------------------------------------------------
extern "C" void kernel_launch(void* const* d_in, const int* in_sizes, int n_in,
                              void* d_out, int out_size)
{
    (void)in_sizes; (void)n_in; (void)out_size;

    const int*   tokens = (const int*)  d_in[0];
    const float* emb    = (const float*)d_in[1];
    const float* W[4] = {(const float*)d_in[2], (const float*)d_in[5],
                         (const float*)d_in[8], (const float*)d_in[11]};
    const float* U[4] = {(const float*)d_in[3], (const float*)d_in[6],
                         (const float*)d_in[9], (const float*)d_in[12]};
    const float* b[4] = {(const float*)d_in[4], (const float*)d_in[7],
                         (const float*)d_in[10], (const float*)d_in[13]};
    const float* Wo = (const float*)d_in[14];
    const float* bo = (const float*)d_in[15];

    float *px = nullptr, *ps = nullptr;
    cudaGetSymbolAddress((void**)&px, g_x);
    cudaGetSymbolAddress((void**)&ps, g_s);

    const dim3 blk(NTHREADS);
    const dim3 gproj(NUNITS / BN, (BATCH * SEQT) / BM);  // 8 x 2560
    const dim3 gstep(NUNITS / BN, BATCH / BM);           // 8 x 32

    // Layer 1 input projection (fused embedding gather)
    embed_proj_kernel<<<gproj, blk>>>(tokens, emb, W[0], b[0], px);

    for (int l = 0; l < 4; l++) {
        if (l > 0)  // input projection for layers 2..4 over the full sequence
            proj_kernel<<<gproj, blk>>>(ps, W[l], b[l], px);
        for (int t = 0; t < SEQT; t++) {
            const float* Ap = (t > 0) ? (ps + (size_t)(t - 1) * NUNITS) : ps;
            step_kernel<<<gstep, blk>>>(Ap, U[l],
                                        px + (size_t)t * NUNITS,
                                        ps + (size_t)t * NUNITS,
                                        t > 0);
        }
    }

    head_kernel<<<BATCH / 8, 256>>>(ps, Wo, bo, (float*)d_out);
}

// round 9
// speedup vs baseline: 3.4394x; 3.4394x over previous
#include <cuda_runtime.h>
#include <cuda_bf16.h>
#include <math.h>

// ---------------- problem constants ----------------
#define BATCHN 2048
#define SEQT   80
#define EMBD   100
#define KPADE  112                 // EMBD padded up to multiple of 16
#define HU     512                 // hidden units
#define ROWSTR (SEQT * HU)         // row stride inside [B,T,H] buffers
#define VOCABN 10000

// ---------------- GEMM tile config ----------------
#define TBM 64
#define TBN 64
#define TKC 64
#define NTHR 256
#define SSTR 72                    // smem K stride in halves (144B, odd 16B phase)

// ---------------- device scratch (sanctioned: no cudaMalloc allowed) ------
__device__ float          g_x [(size_t)BATCHN * SEQT * HU];   // input projections (fp32)
__device__ __nv_bfloat16  g_sb[(size_t)BATCHN * SEQT * HU];   // hidden states (bf16)
__device__ __nv_bfloat16  g_Ub[4 * HU * HU];                  // U weights bf16 [K][N]
__device__ __nv_bfloat16  g_Wb[3 * HU * HU];                  // W2..W4 bf16 [K][N]
__device__ __nv_bfloat16  g_W1b[KPADE * HU];                  // W1 bf16, K zero-padded
__device__ __nv_bfloat16  g_embb[(size_t)VOCABN * KPADE];     // emb bf16, K zero-padded

// ---------------- PTX helpers ----------------
__device__ __forceinline__ unsigned smem_u32(const void* p) {
    return (unsigned)__cvta_generic_to_shared(p);
}
__device__ __forceinline__ void ldsm_x4(unsigned& r0, unsigned& r1, unsigned& r2, unsigned& r3, unsigned a) {
    asm volatile("ldmatrix.sync.aligned.m8n8.x4.shared.b16 {%0,%1,%2,%3},[%4];"
                 : "=r"(r0), "=r"(r1), "=r"(r2), "=r"(r3) : "r"(a));
}
__device__ __forceinline__ void ldsm_x4t(unsigned& r0, unsigned& r1, unsigned& r2, unsigned& r3, unsigned a) {
    asm volatile("ldmatrix.sync.aligned.m8n8.x4.trans.shared.b16 {%0,%1,%2,%3},[%4];"
                 : "=r"(r0), "=r"(r1), "=r"(r2), "=r"(r3) : "r"(a));
}
__device__ __forceinline__ void mma16816(float* c,
                                         unsigned a0, unsigned a1, unsigned a2, unsigned a3,
                                         unsigned b0, unsigned b1) {
    asm volatile("mma.sync.aligned.m16n8k16.row.col.f32.bf16.bf16.f32 "
                 "{%0,%1,%2,%3},{%4,%5,%6,%7},{%8,%9},{%0,%1,%2,%3};"
                 : "+f"(c[0]), "+f"(c[1]), "+f"(c[2]), "+f"(c[3])
                 : "r"(a0), "r"(a1), "r"(a2), "r"(a3), "r"(b0), "r"(b1));
}

// --------------------------------------------------------------------------
// GEMM core (device function; instantiated by plain __global__ wrappers).
// MODE 0: Cf32[row*ldc+col] = acc + biasX[col]                (projection)
// MODE 1: Cb16[row*ldc+col] = tanh(acc + biasX[row*ldx+col])  (RNN step)
// GATHER: A row r = g_embb[tokens[r]] (row stride KPADE)
// Block tile 64x64, 8 warps laid out 2(m) x 4(n), warp tile 32x16.
// --------------------------------------------------------------------------
template<int MODE, int GATHER>
__device__ __forceinline__ void gemm_core(
    const __nv_bfloat16* __restrict__ A, long lda,
    const int* __restrict__ tokens,
    const __nv_bfloat16* __restrict__ B, int ktot,
    const float* __restrict__ biasX, long ldx,
    void* __restrict__ cp, long ldc)
{
    __shared__ __nv_bfloat16 As[TBM * SSTR];
    __shared__ __nv_bfloat16 Bs[TKC * SSTR];

    const int tid  = threadIdx.x;
    const int lane = tid & 31;
    const int wid  = tid >> 5;
    const int wm   = (wid >> 2) * 32;
    const int wn   = (wid & 3) * 16;
    const int rowBase = blockIdx.y * TBM;
    const int colBase = blockIdx.x * TBN;

    float acc[2][2][4];
    #pragma unroll
    for (int i = 0; i < 2; i++) {
        #pragma unroll
        for (int j = 0; j < 2; j++) {
            #pragma unroll
            for (int e = 0; e < 4; e++) { acc[i][j][e] = 0.f; }
        }
    }

    for (int kk = 0; kk < ktot; kk += TKC) {
        // stage A[64 x 64] and B[64 x 64] tiles with 16B loads, zero-padded
        #pragma unroll
        for (int it = 0; it < 2; it++) {
            const int idx = tid + it * NTHR;   // 0..511
            const int r   = idx >> 3;          // 0..63
            const int c8  = (idx & 7) << 3;    // 0,8,...,56

            uint4 va = make_uint4(0u, 0u, 0u, 0u);
            if (kk + c8 < ktot) {
                const __nv_bfloat16* asrc;
                if (GATHER) {
                    asrc = A + (long)tokens[rowBase + r] * KPADE + (kk + c8);
                } else {
                    asrc = A + (long)(rowBase + r) * lda + (kk + c8);
                }
                va = *(const uint4*)asrc;
            }
            *(uint4*)&As[r * SSTR + c8] = va;

            uint4 vb = make_uint4(0u, 0u, 0u, 0u);
            if (kk + r < ktot) {
                vb = *(const uint4*)(B + (long)(kk + r) * HU + colBase + c8);
            }
            *(uint4*)&Bs[r * SSTR + c8] = vb;
        }
        __syncthreads();

        int krem = ktot - kk;
        if (krem > TKC) { krem = TKC; }
        const int ksteps = krem >> 4;

        for (int kt = 0; kt < ksteps; kt++) {
            unsigned a0[4], a1[4], b0, b1, b2, b3;
            {
                unsigned ad = smem_u32(&As[(wm + (lane & 15)) * SSTR
                                           + kt * 16 + ((lane >> 4) << 3)]);
                ldsm_x4(a0[0], a0[1], a0[2], a0[3], ad);
            }
            {
                unsigned ad = smem_u32(&As[(wm + 16 + (lane & 15)) * SSTR
                                           + kt * 16 + ((lane >> 4) << 3)]);
                ldsm_x4(a1[0], a1[1], a1[2], a1[3], ad);
            }
            {
                unsigned ad = smem_u32(&Bs[(kt * 16 + (lane & 15)) * SSTR
                                           + wn + ((lane >> 4) << 3)]);
                ldsm_x4t(b0, b1, b2, b3, ad);
            }
            mma16816(acc[0][0], a0[0], a0[1], a0[2], a0[3], b0, b1);
            mma16816(acc[0][1], a0[0], a0[1], a0[2], a0[3], b2, b3);
            mma16816(acc[1][0], a1[0], a1[1], a1[2], a1[3], b0, b1);
            mma16816(acc[1][1], a1[0], a1[1], a1[2], a1[3], b2, b3);
        }
        __syncthreads();
    }

    // epilogue: c0,c1 -> row = lane>>2, cols 2*(lane&3)+{0,1}; c2,c3 -> row+8
    const int cr = lane >> 2;
    const int cc = (lane & 3) * 2;
    #pragma unroll
    for (int mm = 0; mm < 2; mm++) {
        #pragma unroll
        for (int nn = 0; nn < 2; nn++) {
            const int col = colBase + wn + nn * 8 + cc;
            #pragma unroll
            for (int hf = 0; hf < 2; hf++) {
                const int row = rowBase + wm + mm * 16 + cr + hf * 8;
                const float v0 = acc[mm][nn][hf * 2 + 0];
                const float v1 = acc[mm][nn][hf * 2 + 1];
                if (MODE == 0) {
                    float2* outp = (float2*)((float*)cp + (long)row * ldc + col);
                    *outp = make_float2(v0 + biasX[col], v1 + biasX[col + 1]);
                } else {
                    const float2 xv = *(const float2*)(biasX + (long)row * ldx + col);
                    __nv_bfloat162* outp =
                        (__nv_bfloat162*)((__nv_bfloat16*)cp + (long)row * ldc + col);
                    *outp = __floats2bfloat162_rn(tanhf(v0 + xv.x), tanhf(v1 + xv.y));
                }
            }
        }
    }
}

// ---------------- plain __global__ wrappers (no template launches) --------
__global__ __launch_bounds__(NTHR) void k_proj_gather(
    const __nv_bfloat16* __restrict__ embb, const int* __restrict__ tokens,
    const __nv_bfloat16* __restrict__ w, const float* __restrict__ bias,
    float* __restrict__ outc)
{
    gemm_core<0, 1>(embb, 0, tokens, w, KPADE, bias, 0, outc, HU);
}

__global__ __launch_bounds__(NTHR) void k_proj(
    const __nv_bfloat16* __restrict__ a, long lda,
    const __nv_bfloat16* __restrict__ w, const float* __restrict__ bias,
    float* __restrict__ outc)
{
    gemm_core<0, 0>(a, lda, (const int*)0, w, HU, bias, 0, outc, HU);
}

__global__ __launch_bounds__(NTHR) void k_step(
    const __nv_bfloat16* __restrict__ hprev,
    const __nv_bfloat16* __restrict__ u,
    const float* __restrict__ xin,
    __nv_bfloat16* __restrict__ hout)
{
    gemm_core<1, 0>(hprev, (long)ROWSTR, (const int*)0, u, HU,
                    xin, (long)ROWSTR, hout, (long)ROWSTR);
}

// ---------------- small kernels ----------------
__global__ void k_f2b(const float* __restrict__ src, __nv_bfloat16* __restrict__ dst, int n) {
    int i = blockIdx.x * blockDim.x + threadIdx.x;
    if (i < n) { dst[i] = __float2bfloat16(src[i]); }
}
__global__ void k_padW1(const float* __restrict__ w1, __nv_bfloat16* __restrict__ dst) {
    int i = blockIdx.x * blockDim.x + threadIdx.x;
    if (i < KPADE * HU) {
        int k = i / HU;
        int n = i - k * HU;
        float v = (k < EMBD) ? w1[k * HU + n] : 0.f;
        dst[i] = __float2bfloat16(v);
    }
}
__global__ void k_padEmb(const float* __restrict__ emb, __nv_bfloat16* __restrict__ dst) {
    long i = (long)blockIdx.x * blockDim.x + threadIdx.x;
    if (i < (long)VOCABN * KPADE) {
        int r = (int)(i / KPADE);
        int c = (int)(i - (long)r * KPADE);
        float v = (c < EMBD) ? emb[(long)r * EMBD + c] : 0.f;
        dst[i] = __float2bfloat16(v);
    }
}
// h_0 = tanh(X_0): BATCHN x HU rows, stride ROWSTR
__global__ void k_t0(const float* __restrict__ xin, __nv_bfloat16* __restrict__ hout) {
    long i = (long)blockIdx.x * blockDim.x + threadIdx.x;   // < BATCHN*HU
    int r = (int)(i >> 9);
    int c = (int)(i & 511);
    hout[(long)r * ROWSTR + c] = __float2bfloat16(tanhf(xin[(long)r * ROWSTR + c]));
}
// out[m] = sigmoid(dot(h_T[m], Wo) + bo)
__global__ __launch_bounds__(256) void k_head(
    const __nv_bfloat16* __restrict__ sb, const float* __restrict__ wo,
    const float* __restrict__ bo, float* __restrict__ outp)
{
    const int m = blockIdx.x * 8 + (threadIdx.x >> 5);
    const int lane = threadIdx.x & 31;
    const __nv_bfloat16* hrow = sb + (long)m * ROWSTR + (SEQT - 1) * HU;
    float s = 0.f;
    for (int k = lane; k < HU; k += 32) {
        s = fmaf(__bfloat162float(hrow[k]), wo[k], s);
    }
    #pragma unroll
    for (int o = 16; o > 0; o >>= 1) {
        s += __shfl_xor_sync(0xFFFFFFFFu, s, o);
    }
    if (lane == 0) { outp[m] = 1.f / (1.f + expf(-(s + bo[0]))); }
}

// ---------------- launch ----------------
extern "C" void kernel_launch(void* const* d_in, const int* in_sizes, int n_in,
                              void* d_out, int out_size)
{
    (void)in_sizes; (void)n_in; (void)out_size;

    const int*   tokens = (const int*)  d_in[0];
    const float* emb    = (const float*)d_in[1];
    const float* wmat[4];
    const float* umat[4];
    const float* bvec[4];
    wmat[0] = (const float*)d_in[2];  umat[0] = (const float*)d_in[3];  bvec[0] = (const float*)d_in[4];
    wmat[1] = (const float*)d_in[5];  umat[1] = (const float*)d_in[6];  bvec[1] = (const float*)d_in[7];
    wmat[2] = (const float*)d_in[8];  umat[2] = (const float*)d_in[9];  bvec[2] = (const float*)d_in[10];
    wmat[3] = (const float*)d_in[11]; umat[3] = (const float*)d_in[12]; bvec[3] = (const float*)d_in[13];
    const float* wo = (const float*)d_in[14];
    const float* bo = (const float*)d_in[15];

    float* px = 0;
    __nv_bfloat16* psb = 0;
    __nv_bfloat16* pub = 0;
    __nv_bfloat16* pwb = 0;
    __nv_bfloat16* pw1 = 0;
    __nv_bfloat16* pemb = 0;
    cudaGetSymbolAddress((void**)&px,   g_x);
    cudaGetSymbolAddress((void**)&psb,  g_sb);
    cudaGetSymbolAddress((void**)&pub,  g_Ub);
    cudaGetSymbolAddress((void**)&pwb,  g_Wb);
    cudaGetSymbolAddress((void**)&pw1,  g_W1b);
    cudaGetSymbolAddress((void**)&pemb, g_embb);

    const int nw = HU * HU;
    for (int l = 0; l < 4; l++) {
        k_f2b<<<(nw + 255) / 256, 256>>>(umat[l], pub + (size_t)l * nw, nw);
    }
    for (int l = 1; l < 4; l++) {
        k_f2b<<<(nw + 255) / 256, 256>>>(wmat[l], pwb + (size_t)(l - 1) * nw, nw);
    }
    k_padW1<<<(KPADE * HU + 255) / 256, 256>>>(wmat[0], pw1);
    {
        long nemb = (long)VOCABN * KPADE;
        k_padEmb<<<(unsigned)((nemb + 255) / 256), 256>>>(emb, pemb);
    }

    dim3 blk(NTHR, 1, 1);
    dim3 gproj(HU / TBN, (BATCHN * SEQT) / TBM, 1);   // (8, 2560)
    dim3 gstep(HU / TBN, BATCHN / TBM, 1);            // (8, 32)

    for (int l = 0; l < 4; l++) {
        if (l == 0) {
            k_proj_gather<<<gproj, blk>>>(pemb, tokens, pw1, bvec[0], px);
        } else {
            k_proj<<<gproj, blk>>>(psb, (long)HU, pwb + (size_t)(l - 1) * nw, bvec[l], px);
        }
        k_t0<<<(BATCHN * HU) / 256, 256>>>(px, psb);
        for (int t = 1; t < SEQT; t++) {
            k_step<<<gstep, blk>>>(psb + (size_t)(t - 1) * HU,
                                   pub + (size_t)l * nw,
                                   px + (size_t)t * HU,
                                   psb + (size_t)t * HU);
        }
    }

    k_head<<<BATCHN / 8, 256>>>(psb, wo, bo, (float*)d_out);
}

// round 10
// speedup vs baseline: 3.9155x; 1.1384x over previous
#include <cuda_runtime.h>
#include <cuda_bf16.h>
#include <math.h>

// ---------------- problem constants ----------------
#define BATCHN 2048
#define SEQT   80
#define EMBD   100
#define KPADE  128                 // EMBD padded up to 128 (2 x 64 chunks)
#define HU     512
#define ROWSTR (SEQT * HU)
#define VOCABN 10000
#define MTOT   (BATCHN * SEQT)     // 163840 flat rows for projections
#define NTILES (MTOT / 128)        // 1280 row tiles

// tile config: block tile 128x64, 8 warps = 4(m) x 2(n), warp tile 32x32
#define SSTR 72                    // padded smem row stride in halves

// ---------------- device scratch ----------------
__device__ float          g_x [(size_t)BATCHN * SEQT * HU];   // input projections fp32
__device__ __nv_bfloat16  g_sb[(size_t)BATCHN * SEQT * HU];   // hidden states bf16
__device__ __nv_bfloat16  g_Ub[4 * HU * HU];                  // U bf16 [K][N]
__device__ __nv_bfloat16  g_Wb[3 * HU * HU];                  // W2..W4 bf16 [K][N]
__device__ __nv_bfloat16  g_W1b[KPADE * HU];                  // W1 bf16, K padded
__device__ __nv_bfloat16  g_embb[(size_t)VOCABN * KPADE];     // emb bf16, K padded
__device__ int            g_bar[16];                          // per-row-group barrier

// ---------------- PTX helpers ----------------
__device__ __forceinline__ unsigned smem_u32(const void* p) {
    return (unsigned)__cvta_generic_to_shared(p);
}
__device__ __forceinline__ void ldsm_x4(unsigned& r0, unsigned& r1, unsigned& r2, unsigned& r3, unsigned a) {
    asm volatile("ldmatrix.sync.aligned.m8n8.x4.shared.b16 {%0,%1,%2,%3},[%4];"
                 : "=r"(r0), "=r"(r1), "=r"(r2), "=r"(r3) : "r"(a));
}
__device__ __forceinline__ void ldsm_x4t(unsigned& r0, unsigned& r1, unsigned& r2, unsigned& r3, unsigned a) {
    asm volatile("ldmatrix.sync.aligned.m8n8.x4.trans.shared.b16 {%0,%1,%2,%3},[%4];"
                 : "=r"(r0), "=r"(r1), "=r"(r2), "=r"(r3) : "r"(a));
}
__device__ __forceinline__ void mma16816(float* c,
                                         unsigned a0, unsigned a1, unsigned a2, unsigned a3,
                                         unsigned b0, unsigned b1) {
    asm volatile("mma.sync.aligned.m16n8k16.row.col.f32.bf16.bf16.f32 "
                 "{%0,%1,%2,%3},{%4,%5,%6,%7},{%8,%9},{%0,%1,%2,%3};"
                 : "+f"(c[0]), "+f"(c[1]), "+f"(c[2]), "+f"(c[3])
                 : "r"(a0), "r"(a1), "r"(a2), "r"(a3), "r"(b0), "r"(b1));
}
__device__ __forceinline__ void cp16(void* dst, const void* src) {
    unsigned d = smem_u32(dst);
    asm volatile("cp.async.cg.shared.global [%0],[%1],16;" :: "r"(d), "l"(src));
}
__device__ __forceinline__ void cp_commit() { asm volatile("cp.async.commit_group;"); }
__device__ __forceinline__ void cp_wait0()  { asm volatile("cp.async.wait_group 0;"); }
__device__ __forceinline__ void cp_wait1()  { asm volatile("cp.async.wait_group 1;"); }
__device__ __forceinline__ int  ld_acq(const int* p) {
    int v;
    asm volatile("ld.acquire.gpu.s32 %0,[%1];" : "=r"(v) : "l"(p));
    return v;
}

// ---------------- shared mma building blocks ----------------
// one k16 slice: A frags from Ab (128 x 64 chunk, stride SSTR), B frags from
// Uk (64 x 64 chunk of resident weight slice, stride SSTR), acc[2][4][4].
__device__ __forceinline__ void mma_k16(float acc[2][4][4],
                                        const __nv_bfloat16* Ab,
                                        const __nv_bfloat16* Uk,
                                        int kt, int lane, int wm, int wn)
{
    unsigned af0[4];
    unsigned af1[4];
    unsigned bf0[4];
    unsigned bf1[4];
    {
        unsigned ad = smem_u32(Ab + (wm + (lane & 15)) * SSTR + kt * 16 + ((lane >> 4) << 3));
        ldsm_x4(af0[0], af0[1], af0[2], af0[3], ad);
    }
    {
        unsigned ad = smem_u32(Ab + (wm + 16 + (lane & 15)) * SSTR + kt * 16 + ((lane >> 4) << 3));
        ldsm_x4(af1[0], af1[1], af1[2], af1[3], ad);
    }
    {
        unsigned ad = smem_u32(Uk + (kt * 16 + (lane & 15)) * SSTR + wn + ((lane >> 4) << 3));
        ldsm_x4t(bf0[0], bf0[1], bf0[2], bf0[3], ad);
    }
    {
        unsigned ad = smem_u32(Uk + (kt * 16 + (lane & 15)) * SSTR + wn + 16 + ((lane >> 4) << 3));
        ldsm_x4t(bf1[0], bf1[1], bf1[2], bf1[3], ad);
    }
    mma16816(acc[0][0], af0[0], af0[1], af0[2], af0[3], bf0[0], bf0[1]);
    mma16816(acc[0][1], af0[0], af0[1], af0[2], af0[3], bf0[2], bf0[3]);
    mma16816(acc[0][2], af0[0], af0[1], af0[2], af0[3], bf1[0], bf1[1]);
    mma16816(acc[0][3], af0[0], af0[1], af0[2], af0[3], bf1[2], bf1[3]);
    mma16816(acc[1][0], af1[0], af1[1], af1[2], af1[3], bf0[0], bf0[1]);
    mma16816(acc[1][1], af1[0], af1[1], af1[2], af1[3], bf0[2], bf0[3]);
    mma16816(acc[1][2], af1[0], af1[1], af1[2], af1[3], bf1[0], bf1[1]);
    mma16816(acc[1][3], af1[0], af1[1], af1[2], af1[3], bf1[2], bf1[3]);
}

// async-load a 128x64 A chunk (16B per cp.async); src already at (row0, k0)
__device__ __forceinline__ void load_chunk(__nv_bfloat16* dst,
                                           const __nv_bfloat16* src, long lda, int tid)
{
    #pragma unroll
    for (int j = 0; j < 4; j++) {
        int idx = tid + j * 256;
        int r   = idx >> 3;
        int c8  = (idx & 7) << 3;
        cp16(dst + r * SSTR + c8, src + (long)r * lda + c8);
    }
}
// gathered variant: row r = embb[tokens[rowBase + r]], row stride KPADE
__device__ __forceinline__ void load_chunk_g(__nv_bfloat16* dst,
                                             const __nv_bfloat16* embb,
                                             const int* toks, int rowBase, int kofs, int tid)
{
    #pragma unroll
    for (int j = 0; j < 4; j++) {
        int idx = tid + j * 256;
        int r   = idx >> 3;
        int c8  = (idx & 7) << 3;
        long tr = toks[rowBase + r];
        cp16(dst + r * SSTR + c8, embb + tr * KPADE + kofs + c8);
    }
}

#define SMEM_DYN ((512 * SSTR + 2 * 128 * SSTR) * 2)   // 110592 bytes

// --------------------------------------------------------------------------
// Projection kernel: out[M,512] = A[M,ktot] @ W[ktot,512] + bias (fp32 out).
// W col-slice resident in smem; each block loops row tiles (stride gridDim.y).
// --------------------------------------------------------------------------
__global__ __launch_bounds__(256) void k_projx(
    const __nv_bfloat16* __restrict__ amat, const int* __restrict__ toks,
    const __nv_bfloat16* __restrict__ wmat, const float* __restrict__ bias,
    float* __restrict__ outc, int ktot, int gather)
{
    extern __shared__ __align__(16) char smraw[];
    __nv_bfloat16* Us  = (__nv_bfloat16*)smraw;           // [ktot][SSTR]
    __nv_bfloat16* Ab0 = Us + 512 * SSTR;                 // [128][SSTR]
    __nv_bfloat16* Ab1 = Ab0 + 128 * SSTR;

    const int tid  = threadIdx.x;
    const int lane = tid & 31;
    const int wid  = tid >> 5;
    const int wm   = (wid >> 1) * 32;
    const int wn   = (wid & 1) * 32;
    const int colBase = blockIdx.x * 64;

    for (int i = tid; i < ktot * 8; i += 256) {
        int r  = i >> 3;
        int c8 = (i & 7) << 3;
        *(uint4*)&Us[r * SSTR + c8] = *(const uint4*)&wmat[(long)r * HU + colBase + c8];
    }
    __syncthreads();

    const int nch = ktot >> 6;
    const int cr = lane >> 2;
    const int cc = (lane & 3) * 2;

    for (int tile = blockIdx.y; tile < NTILES; tile += gridDim.y) {
        const int rowBase = tile * 128;
        if (gather) { load_chunk_g(Ab0, amat, toks, rowBase, 0, tid); }
        else        { load_chunk(Ab0, amat + (long)rowBase * ktot, (long)ktot, tid); }
        cp_commit();

        float acc[2][4][4];
        #pragma unroll
        for (int i = 0; i < 2; i++) {
            #pragma unroll
            for (int j = 0; j < 4; j++) {
                #pragma unroll
                for (int e = 0; e < 4; e++) { acc[i][j][e] = 0.f; }
            }
        }

        for (int kc = 0; kc < nch; kc++) {
            __nv_bfloat16* cur = (kc & 1) ? Ab1 : Ab0;
            __nv_bfloat16* nxt = (kc & 1) ? Ab0 : Ab1;
            if (kc + 1 < nch) {
                if (gather) { load_chunk_g(nxt, amat, toks, rowBase, (kc + 1) * 64, tid); }
                else        { load_chunk(nxt, amat + (long)rowBase * ktot + (kc + 1) * 64, (long)ktot, tid); }
                cp_commit();
                cp_wait1();
            } else {
                cp_wait0();
            }
            __syncthreads();
            const __nv_bfloat16* Uk = Us + kc * 64 * SSTR;
            for (int kt = 0; kt < 4; kt++) { mma_k16(acc, cur, Uk, kt, lane, wm, wn); }
            __syncthreads();
        }

        #pragma unroll
        for (int mm = 0; mm < 2; mm++) {
            #pragma unroll
            for (int nn = 0; nn < 4; nn++) {
                const int col = colBase + wn + nn * 8 + cc;
                #pragma unroll
                for (int hf = 0; hf < 2; hf++) {
                    const int row = rowBase + wm + mm * 16 + cr + hf * 8;
                    float2 o;
                    o.x = acc[mm][nn][hf * 2 + 0] + bias[col];
                    o.y = acc[mm][nn][hf * 2 + 1] + bias[col + 1];
                    *(float2*)&outc[(long)row * HU + col] = o;
                }
            }
        }
    }
}

// --------------------------------------------------------------------------
// Persistent per-layer recurrence kernel. Grid (8, 16) = 128 co-resident
// blocks; block = rows [rb*128, +128) x cols [cb*64, +64). U slice resident
// in smem. Per-row-group barrier via monotonic atomic counter g_bar[rb].
// --------------------------------------------------------------------------
__global__ __launch_bounds__(256) void k_layer(
    const __nv_bfloat16* __restrict__ u,   // [512][512]
    const float* __restrict__ xin,         // g_x base [B][T][H]
    __nv_bfloat16* __restrict__ hseq,      // g_sb base [B][T][H]
    int* __restrict__ bar)
{
    extern __shared__ __align__(16) char smraw[];
    __nv_bfloat16* Us  = (__nv_bfloat16*)smraw;
    __nv_bfloat16* Ab0 = Us + 512 * SSTR;
    __nv_bfloat16* Ab1 = Ab0 + 128 * SSTR;

    const int tid  = threadIdx.x;
    const int lane = tid & 31;
    const int wid  = tid >> 5;
    const int wm   = (wid >> 1) * 32;
    const int wn   = (wid & 1) * 32;
    const int rb   = blockIdx.y;
    const int rowBase = rb * 128;
    const int colBase = blockIdx.x * 64;

    for (int i = tid; i < 512 * 8; i += 256) {
        int r  = i >> 3;
        int c8 = (i & 7) << 3;
        *(uint4*)&Us[r * SSTR + c8] = *(const uint4*)&u[(long)r * HU + colBase + c8];
    }

    // t = 0: h0 = tanh(X0)
    for (int i = tid; i < 128 * 64; i += 256) {
        int r = i >> 6;
        int c = i & 63;
        long off = (long)(rowBase + r) * ROWSTR + colBase + c;
        hseq[off] = __float2bfloat16(tanhf(xin[off]));
    }
    __threadfence();
    __syncthreads();
    if (tid == 0) { atomicAdd(bar + rb, 1); }

    const int cr = lane >> 2;
    const int cc = (lane & 3) * 2;

    for (int t = 1; t < SEQT; t++) {
        if (tid == 0) {
            while (ld_acq(bar + rb) < 8 * t) { __nanosleep(32); }
        }
        __syncthreads();

        const __nv_bfloat16* aprev = hseq + (long)rowBase * ROWSTR + (long)(t - 1) * HU;
        load_chunk(Ab0, aprev, (long)ROWSTR, tid);
        cp_commit();

        float acc[2][4][4];
        #pragma unroll
        for (int i = 0; i < 2; i++) {
            #pragma unroll
            for (int j = 0; j < 4; j++) {
                #pragma unroll
                for (int e = 0; e < 4; e++) { acc[i][j][e] = 0.f; }
            }
        }

        for (int kc = 0; kc < 8; kc++) {
            __nv_bfloat16* cur = (kc & 1) ? Ab1 : Ab0;
            __nv_bfloat16* nxt = (kc & 1) ? Ab0 : Ab1;
            if (kc < 7) {
                load_chunk(nxt, aprev + (kc + 1) * 64, (long)ROWSTR, tid);
                cp_commit();
                cp_wait1();
            } else {
                cp_wait0();
            }
            __syncthreads();
            const __nv_bfloat16* Uk = Us + kc * 64 * SSTR;
            for (int kt = 0; kt < 4; kt++) { mma_k16(acc, cur, Uk, kt, lane, wm, wn); }
            __syncthreads();
        }

        #pragma unroll
        for (int mm = 0; mm < 2; mm++) {
            #pragma unroll
            for (int nn = 0; nn < 4; nn++) {
                const int col = colBase + wn + nn * 8 + cc;
                #pragma unroll
                for (int hf = 0; hf < 2; hf++) {
                    const int row = rowBase + wm + mm * 16 + cr + hf * 8;
                    long off = (long)row * ROWSTR + (long)t * HU + col;
                    float2 xv = *(const float2*)&xin[off];
                    float v0 = tanhf(acc[mm][nn][hf * 2 + 0] + xv.x);
                    float v1 = tanhf(acc[mm][nn][hf * 2 + 1] + xv.y);
                    *(__nv_bfloat162*)&hseq[off] = __floats2bfloat162_rn(v0, v1);
                }
            }
        }
        __threadfence();
        __syncthreads();
        if (tid == 0) { atomicAdd(bar + rb, 1); }
    }
}

// ---------------- small kernels ----------------
__global__ void k_reset(int* __restrict__ bar) {
    if (threadIdx.x < 16) { bar[threadIdx.x] = 0; }
}
__global__ void k_f2b(const float* __restrict__ src, __nv_bfloat16* __restrict__ dst, int n) {
    int i = blockIdx.x * blockDim.x + threadIdx.x;
    if (i < n) { dst[i] = __float2bfloat16(src[i]); }
}
__global__ void k_padW1(const float* __restrict__ w1, __nv_bfloat16* __restrict__ dst) {
    int i = blockIdx.x * blockDim.x + threadIdx.x;
    if (i < KPADE * HU) {
        int k = i / HU;
        int n = i - k * HU;
        float v = (k < EMBD) ? w1[k * HU + n] : 0.f;
        dst[i] = __float2bfloat16(v);
    }
}
__global__ void k_padEmb(const float* __restrict__ emb, __nv_bfloat16* __restrict__ dst) {
    long i = (long)blockIdx.x * blockDim.x + threadIdx.x;
    if (i < (long)VOCABN * KPADE) {
        int r = (int)(i / KPADE);
        int c = (int)(i - (long)r * KPADE);
        float v = (c < EMBD) ? emb[(long)r * EMBD + c] : 0.f;
        dst[i] = __float2bfloat16(v);
    }
}
__global__ __launch_bounds__(256) void k_head(
    const __nv_bfloat16* __restrict__ sb, const float* __restrict__ wo,
    const float* __restrict__ bo, float* __restrict__ outp)
{
    const int m = blockIdx.x * 8 + (threadIdx.x >> 5);
    const int lane = threadIdx.x & 31;
    const __nv_bfloat16* hrow = sb + (long)m * ROWSTR + (SEQT - 1) * HU;
    float s = 0.f;
    for (int k = lane; k < HU; k += 32) {
        s = fmaf(__bfloat162float(hrow[k]), wo[k], s);
    }
    #pragma unroll
    for (int o = 16; o > 0; o >>= 1) {
        s += __shfl_xor_sync(0xFFFFFFFFu, s, o);
    }
    if (lane == 0) { outp[m] = 1.f / (1.f + expf(-(s + bo[0]))); }
}

// ---------------- launch ----------------
extern "C" void kernel_launch(void* const* d_in, const int* in_sizes, int n_in,
                              void* d_out, int out_size)
{
    (void)in_sizes; (void)n_in; (void)out_size;

    const int*   tokens = (const int*)  d_in[0];
    const float* emb    = (const float*)d_in[1];
    const float* wmat[4];
    const float* umat[4];
    const float* bvec[4];
    wmat[0] = (const float*)d_in[2];  umat[0] = (const float*)d_in[3];  bvec[0] = (const float*)d_in[4];
    wmat[1] = (const float*)d_in[5];  umat[1] = (const float*)d_in[6];  bvec[1] = (const float*)d_in[7];
    wmat[2] = (const float*)d_in[8];  umat[2] = (const float*)d_in[9];  bvec[2] = (const float*)d_in[10];
    wmat[3] = (const float*)d_in[11]; umat[3] = (const float*)d_in[12]; bvec[3] = (const float*)d_in[13];
    const float* wo = (const float*)d_in[14];
    const float* bo = (const float*)d_in[15];

    float* px = 0;
    __nv_bfloat16* psb = 0;
    __nv_bfloat16* pub = 0;
    __nv_bfloat16* pwb = 0;
    __nv_bfloat16* pw1 = 0;
    __nv_bfloat16* pemb = 0;
    int* pbar = 0;
    cudaGetSymbolAddress((void**)&px,   g_x);
    cudaGetSymbolAddress((void**)&psb,  g_sb);
    cudaGetSymbolAddress((void**)&pub,  g_Ub);
    cudaGetSymbolAddress((void**)&pwb,  g_Wb);
    cudaGetSymbolAddress((void**)&pw1,  g_W1b);
    cudaGetSymbolAddress((void**)&pemb, g_embb);
    cudaGetSymbolAddress((void**)&pbar, g_bar);

    cudaFuncSetAttribute(k_projx, cudaFuncAttributeMaxDynamicSharedMemorySize, SMEM_DYN);
    cudaFuncSetAttribute(k_layer, cudaFuncAttributeMaxDynamicSharedMemorySize, SMEM_DYN);

    const int nw = HU * HU;
    for (int l = 0; l < 4; l++) {
        k_f2b<<<(nw + 255) / 256, 256>>>(umat[l], pub + (size_t)l * nw, nw);
    }
    for (int l = 1; l < 4; l++) {
        k_f2b<<<(nw + 255) / 256, 256>>>(wmat[l], pwb + (size_t)(l - 1) * nw, nw);
    }
    k_padW1<<<(KPADE * HU + 255) / 256, 256>>>(wmat[0], pw1);
    {
        long nemb = (long)VOCABN * KPADE;
        k_padEmb<<<(unsigned)((nemb + 255) / 256), 256>>>(emb, pemb);
    }

    dim3 blk(256, 1, 1);
    dim3 gproj(8, 160, 1);     // 1280 blocks, each loops 8 row tiles
    dim3 glayer(8, 16, 1);     // 128 persistent blocks

    for (int l = 0; l < 4; l++) {
        if (l == 0) {
            k_projx<<<gproj, blk, SMEM_DYN>>>(pemb, tokens, pw1, bvec[0], px, KPADE, 1);
        } else {
            k_projx<<<gproj, blk, SMEM_DYN>>>(psb, (const int*)0,
                                              pwb + (size_t)(l - 1) * nw, bvec[l], px, HU, 0);
        }
        k_reset<<<1, 32>>>(pbar);
        k_layer<<<glayer, blk, SMEM_DYN>>>(pub + (size_t)l * nw, px, psb, pbar);
    }

    k_head<<<BATCHN / 8, 256>>>(psb, wo, bo, (float*)d_out);
}

// round 11
// speedup vs baseline: 4.3215x; 1.1037x over previous
#include <cuda_runtime.h>
#include <cuda_bf16.h>
#include <math.h>

// ---------------- problem constants ----------------
#define BATCHN 2048
#define SEQT   80
#define EMBD   100
#define KPADE  128                 // EMBD padded to 128 (2 x 64 chunks)
#define HU     512
#define ROWSTR (SEQT * HU)
#define VOCABN 10000
#define MTOT   (BATCHN * SEQT)
#define NTILES (MTOT / 128)        // 1280

#define SSTR 72                    // padded smem row stride in halves

// ---------------- device scratch ----------------
__device__ __nv_bfloat16  g_x [(size_t)BATCHN * SEQT * HU];   // input projections bf16
__device__ __nv_bfloat16  g_sb[(size_t)BATCHN * SEQT * HU];   // hidden states bf16
__device__ __nv_bfloat16  g_Ub[4 * HU * HU];                  // U bf16 [K][N]
__device__ __nv_bfloat16  g_Wb[3 * HU * HU];                  // W2..W4 bf16 [K][N]
__device__ __nv_bfloat16  g_W1b[KPADE * HU];                  // W1 bf16, K padded
__device__ __nv_bfloat16  g_embb[(size_t)VOCABN * KPADE];     // emb bf16, K padded
__device__ int            g_flags[4 * 16 * 8];                // per layer/rowgroup/colblock

// ---------------- PTX helpers ----------------
__device__ __forceinline__ unsigned smem_u32(const void* p) {
    return (unsigned)__cvta_generic_to_shared(p);
}
__device__ __forceinline__ void ldsm_x4(unsigned& r0, unsigned& r1, unsigned& r2, unsigned& r3, unsigned a) {
    asm volatile("ldmatrix.sync.aligned.m8n8.x4.shared.b16 {%0,%1,%2,%3},[%4];"
                 : "=r"(r0), "=r"(r1), "=r"(r2), "=r"(r3) : "r"(a));
}
__device__ __forceinline__ void ldsm_x4t(unsigned& r0, unsigned& r1, unsigned& r2, unsigned& r3, unsigned a) {
    asm volatile("ldmatrix.sync.aligned.m8n8.x4.trans.shared.b16 {%0,%1,%2,%3},[%4];"
                 : "=r"(r0), "=r"(r1), "=r"(r2), "=r"(r3) : "r"(a));
}
__device__ __forceinline__ void mma16816(float* c,
                                         unsigned a0, unsigned a1, unsigned a2, unsigned a3,
                                         unsigned b0, unsigned b1) {
    asm volatile("mma.sync.aligned.m16n8k16.row.col.f32.bf16.bf16.f32 "
                 "{%0,%1,%2,%3},{%4,%5,%6,%7},{%8,%9},{%0,%1,%2,%3};"
                 : "+f"(c[0]), "+f"(c[1]), "+f"(c[2]), "+f"(c[3])
                 : "r"(a0), "r"(a1), "r"(a2), "r"(a3), "r"(b0), "r"(b1));
}
__device__ __forceinline__ void cp16(void* dst, const void* src) {
    unsigned d = smem_u32(dst);
    asm volatile("cp.async.cg.shared.global [%0],[%1],16;" :: "r"(d), "l"(src));
}
__device__ __forceinline__ void cp_commit() { asm volatile("cp.async.commit_group;"); }
__device__ __forceinline__ void cp_wait0()  { asm volatile("cp.async.wait_group 0;"); }
__device__ __forceinline__ void cp_wait1()  { asm volatile("cp.async.wait_group 1;"); }
__device__ __forceinline__ void cp_wait2()  { asm volatile("cp.async.wait_group 2;"); }
__device__ __forceinline__ int ld_acq(const int* p) {
    int v;
    asm volatile("ld.acquire.gpu.global.s32 %0,[%1];" : "=r"(v) : "l"(p) : "memory");
    return v;
}
__device__ __forceinline__ void st_rel(int* p, int v) {
    asm volatile("st.release.gpu.global.s32 [%0],%1;" :: "l"(p), "r"(v) : "memory");
}
__device__ __forceinline__ float tanh_fast(float x) {
    float y;
    asm("tanh.approx.f32 %0,%1;" : "=f"(y) : "f"(x));
    return y;
}

// ---------------- mma building block ----------------
// one k16 slice: A frags (128x64 chunk, stride SSTR), B frags from resident
// U chunk (64x64, stride SSTR). acc[2][4][4]. warp tile 32(m) x 32(n).
__device__ __forceinline__ void mma_k16(float acc[2][4][4],
                                        const __nv_bfloat16* Ab,
                                        const __nv_bfloat16* Uk,
                                        int kt, int lane, int wm, int wn)
{
    unsigned af0[4];
    unsigned af1[4];
    unsigned bf0[4];
    unsigned bf1[4];
    {
        unsigned ad = smem_u32(Ab + (wm + (lane & 15)) * SSTR + kt * 16 + ((lane >> 4) << 3));
        ldsm_x4(af0[0], af0[1], af0[2], af0[3], ad);
    }
    {
        unsigned ad = smem_u32(Ab + (wm + 16 + (lane & 15)) * SSTR + kt * 16 + ((lane >> 4) << 3));
        ldsm_x4(af1[0], af1[1], af1[2], af1[3], ad);
    }
    {
        unsigned ad = smem_u32(Uk + (kt * 16 + (lane & 15)) * SSTR + wn + ((lane >> 4) << 3));
        ldsm_x4t(bf0[0], bf0[1], bf0[2], bf0[3], ad);
    }
    {
        unsigned ad = smem_u32(Uk + (kt * 16 + (lane & 15)) * SSTR + wn + 16 + ((lane >> 4) << 3));
        ldsm_x4t(bf1[0], bf1[1], bf1[2], bf1[3], ad);
    }
    mma16816(acc[0][0], af0[0], af0[1], af0[2], af0[3], bf0[0], bf0[1]);
    mma16816(acc[0][1], af0[0], af0[1], af0[2], af0[3], bf0[2], bf0[3]);
    mma16816(acc[0][2], af0[0], af0[1], af0[2], af0[3], bf1[0], bf1[1]);
    mma16816(acc[0][3], af0[0], af0[1], af0[2], af0[3], bf1[2], bf1[3]);
    mma16816(acc[1][0], af1[0], af1[1], af1[2], af1[3], bf0[0], bf0[1]);
    mma16816(acc[1][1], af1[0], af1[1], af1[2], af1[3], bf0[2], bf0[3]);
    mma16816(acc[1][2], af1[0], af1[1], af1[2], af1[3], bf1[0], bf1[1]);
    mma16816(acc[1][3], af1[0], af1[1], af1[2], af1[3], bf1[2], bf1[3]);
}

// async-load a 128x64 bf16 chunk; src at (row0, k0), row stride lda
__device__ __forceinline__ void load_chunk(__nv_bfloat16* dst,
                                           const __nv_bfloat16* src, long lda, int tid)
{
    #pragma unroll
    for (int j = 0; j < 4; j++) {
        int idx = tid + j * 256;
        int r   = idx >> 3;
        int c8  = (idx & 7) << 3;
        cp16(dst + r * SSTR + c8, src + (long)r * lda + c8);
    }
}
__device__ __forceinline__ void load_chunk_g(__nv_bfloat16* dst,
                                             const __nv_bfloat16* embb,
                                             const int* toks, int rowBase, int kofs, int tid)
{
    #pragma unroll
    for (int j = 0; j < 4; j++) {
        int idx = tid + j * 256;
        int r   = idx >> 3;
        int c8  = (idx & 7) << 3;
        long tr = toks[rowBase + r];
        cp16(dst + r * SSTR + c8, embb + tr * KPADE + kofs + c8);
    }
}

#define SMEM_PROJ ((512 * SSTR + 2 * 128 * SSTR) * 2)   // 110592
#define SMEM_LAYER ((512 * SSTR + 3 * 128 * SSTR) * 2)  // 129024

// --------------------------------------------------------------------------
// Projection: out_bf16[M,512] = A[M,ktot] @ W[ktot,512] + bias.
// Persistent: W col-slice resident; each block loops row tiles.
// --------------------------------------------------------------------------
__global__ __launch_bounds__(256) void k_projx(
    const __nv_bfloat16* __restrict__ amat, const int* __restrict__ toks,
    const __nv_bfloat16* __restrict__ wmat, const float* __restrict__ bias,
    __nv_bfloat16* __restrict__ outc, int ktot, int gather)
{
    extern __shared__ __align__(16) char smraw[];
    __nv_bfloat16* Us  = (__nv_bfloat16*)smraw;
    __nv_bfloat16* Ab0 = Us + 512 * SSTR;
    __nv_bfloat16* Ab1 = Ab0 + 128 * SSTR;

    const int tid  = threadIdx.x;
    const int lane = tid & 31;
    const int wid  = tid >> 5;
    const int wm   = (wid >> 1) * 32;
    const int wn   = (wid & 1) * 32;
    const int colBase = blockIdx.x * 64;

    for (int i = tid; i < ktot * 8; i += 256) {
        int r  = i >> 3;
        int c8 = (i & 7) << 3;
        *(uint4*)&Us[r * SSTR + c8] = *(const uint4*)&wmat[(long)r * HU + colBase + c8];
    }
    __syncthreads();

    const int nch = ktot >> 6;
    const int cr = lane >> 2;
    const int cc = (lane & 3) * 2;

    for (int tile = blockIdx.y; tile < NTILES; tile += gridDim.y) {
        const int rowBase = tile * 128;
        if (gather) { load_chunk_g(Ab0, amat, toks, rowBase, 0, tid); }
        else        { load_chunk(Ab0, amat + (long)rowBase * ktot, (long)ktot, tid); }
        cp_commit();

        float acc[2][4][4];
        #pragma unroll
        for (int i = 0; i < 2; i++) {
            #pragma unroll
            for (int j = 0; j < 4; j++) {
                #pragma unroll
                for (int e = 0; e < 4; e++) { acc[i][j][e] = 0.f; }
            }
        }

        for (int kc = 0; kc < nch; kc++) {
            __nv_bfloat16* cur = (kc & 1) ? Ab1 : Ab0;
            __nv_bfloat16* nxt = (kc & 1) ? Ab0 : Ab1;
            if (kc + 1 < nch) {
                if (gather) { load_chunk_g(nxt, amat, toks, rowBase, (kc + 1) * 64, tid); }
                else        { load_chunk(nxt, amat + (long)rowBase * ktot + (kc + 1) * 64, (long)ktot, tid); }
                cp_commit();
                cp_wait1();
            } else {
                cp_wait0();
            }
            __syncthreads();
            const __nv_bfloat16* Uk = Us + kc * 64 * SSTR;
            for (int kt = 0; kt < 4; kt++) { mma_k16(acc, cur, Uk, kt, lane, wm, wn); }
            __syncthreads();
        }

        #pragma unroll
        for (int mm = 0; mm < 2; mm++) {
            #pragma unroll
            for (int nn = 0; nn < 4; nn++) {
                const int col = colBase + wn + nn * 8 + cc;
                #pragma unroll
                for (int hf = 0; hf < 2; hf++) {
                    const int row = rowBase + wm + mm * 16 + cr + hf * 8;
                    float v0 = acc[mm][nn][hf * 2 + 0] + bias[col];
                    float v1 = acc[mm][nn][hf * 2 + 1] + bias[col + 1];
                    *(__nv_bfloat162*)&outc[(long)row * HU + col] = __floats2bfloat162_rn(v0, v1);
                }
            }
        }
    }
}

// --------------------------------------------------------------------------
// Persistent per-layer recurrence. Grid (8,16) = 128 resident blocks.
// Per-producer flags: flag[rb*8+cb] = steps completed. A block starts each
// step with its OWN chunk (kept in smem from its epilogue), wraps over the
// other 7 with a 3-buffer cp.async ring; waits overlap with compute.
// --------------------------------------------------------------------------
__global__ __launch_bounds__(256) void k_layer(
    const __nv_bfloat16* __restrict__ u,
    const __nv_bfloat16* __restrict__ xin,
    __nv_bfloat16* __restrict__ hseq,
    int* __restrict__ flg)
{
    extern __shared__ __align__(16) char smraw[];
    __nv_bfloat16* Us = (__nv_bfloat16*)smraw;
    __nv_bfloat16* Ab0 = Us + 512 * SSTR;
    __nv_bfloat16* Ab1 = Ab0 + 128 * SSTR;
    __nv_bfloat16* Ab2 = Ab1 + 128 * SSTR;
    __nv_bfloat16* ring[3];
    ring[0] = Ab0; ring[1] = Ab1; ring[2] = Ab2;

    const int tid  = threadIdx.x;
    const int lane = tid & 31;
    const int wid  = tid >> 5;
    const int wm   = (wid >> 1) * 32;
    const int wn   = (wid & 1) * 32;
    const int cb   = blockIdx.x;
    const int rb   = blockIdx.y;
    const int rowBase = rb * 128;
    const int colBase = cb * 64;
    int* fbase  = flg + rb * 8;
    int* myflag = fbase + cb;

    for (int i = tid; i < 512 * 8; i += 256) {
        int r  = i >> 3;
        int c8 = (i & 7) << 3;
        *(uint4*)&Us[r * SSTR + c8] = *(const uint4*)&u[(long)r * HU + colBase + c8];
    }

    // t=0: h0 = tanh(x0) -> gmem + own-chunk smem (Ab0)
    for (int i = tid; i < 128 * 64; i += 256) {
        int r = i >> 6;
        int c = i & 63;
        long off = (long)(rowBase + r) * ROWSTR + colBase + c;
        float v = tanh_fast(__bfloat162float(xin[off]));
        __nv_bfloat16 hv = __float2bfloat16(v);
        hseq[off] = hv;
        Ab0[r * SSTR + c] = hv;
    }
    __syncthreads();
    if (tid == 0) { st_rel(myflag, 1); }

    const int cr = lane >> 2;
    const int cc = (lane & 3) * 2;

    for (int t = 1; t < SEQT; t++) {
        const __nv_bfloat16* hprev = hseq + (long)rowBase * ROWSTR + (long)(t - 1) * HU;

        // prologue: stage 1 (own stage 0 already in Ab0 from epilogue/h0)
        const int kc1 = (cb + 1) & 7;
        if (tid == 0) { while (ld_acq(fbase + kc1) < t) { } }
        __syncthreads();                                   // flags + own-chunk smem visible
        load_chunk(ring[1], hprev + kc1 * 64, (long)ROWSTR, tid);
        cp_commit();

        // hoist x_t loads (bf16x2), overlap with GEMM
        unsigned xr[16];
        {
            int q = 0;
            #pragma unroll
            for (int mm = 0; mm < 2; mm++) {
                #pragma unroll
                for (int nn = 0; nn < 4; nn++) {
                    const int col = colBase + wn + nn * 8 + cc;
                    #pragma unroll
                    for (int hf = 0; hf < 2; hf++) {
                        const int row = rowBase + wm + mm * 16 + cr + hf * 8;
                        xr[q] = *(const unsigned*)&xin[(long)row * ROWSTR + (long)t * HU + col];
                        q++;
                    }
                }
            }
        }

        float acc[2][4][4];
        #pragma unroll
        for (int i = 0; i < 2; i++) {
            #pragma unroll
            for (int j = 0; j < 4; j++) {
                #pragma unroll
                for (int e = 0; e < 4; e++) { acc[i][j][e] = 0.f; }
            }
        }

        #pragma unroll
        for (int i = 0; i < 8; i++) {
            const int kci = (cb + i) & 7;
            if (i + 2 < 8) {
                const int kcn = (cb + i + 2) & 7;
                if (tid == 0) { while (ld_acq(fbase + kcn) < t) { } }
                __syncthreads();                           // buffer (i+2)%3 free + flag ack
                load_chunk(ring[(i + 2) % 3], hprev + kcn * 64, (long)ROWSTR, tid);
                cp_commit();
                if (i > 0) { cp_wait2(); }
            } else if (i + 1 < 8) {
                cp_wait1();
            } else {
                cp_wait0();
            }
            __syncthreads();                               // stage i data visible
            const __nv_bfloat16* Uk = Us + kci * 64 * SSTR;
            for (int kt = 0; kt < 4; kt++) { mma_k16(acc, ring[i % 3], Uk, kt, lane, wm, wn); }
        }

        // epilogue: h_t = tanh(acc + x_t) -> gmem + own-chunk smem (Ab0)
        {
            int q = 0;
            #pragma unroll
            for (int mm = 0; mm < 2; mm++) {
                #pragma unroll
                for (int nn = 0; nn < 4; nn++) {
                    const int col = colBase + wn + nn * 8 + cc;
                    #pragma unroll
                    for (int hf = 0; hf < 2; hf++) {
                        const int row = rowBase + wm + mm * 16 + cr + hf * 8;
                        const int lr  = wm + mm * 16 + cr + hf * 8;
                        const int lc  = wn + nn * 8 + cc;
                        float2 xv = __bfloat1622float2(*(const __nv_bfloat162*)&xr[q]);
                        q++;
                        float v0 = tanh_fast(acc[mm][nn][hf * 2 + 0] + xv.x);
                        float v1 = tanh_fast(acc[mm][nn][hf * 2 + 1] + xv.y);
                        __nv_bfloat162 hv = __floats2bfloat162_rn(v0, v1);
                        *(__nv_bfloat162*)&hseq[(long)row * ROWSTR + (long)t * HU + col] = hv;
                        *(__nv_bfloat162*)&Ab0[lr * SSTR + lc] = hv;
                    }
                }
            }
        }
        __syncthreads();
        if (tid == 0) { st_rel(myflag, t + 1); }
    }
}

// ---------------- conversion / misc kernels ----------------
struct SrcPtrs { const float* p[7]; };

__global__ void k_convertW(SrcPtrs sp, __nv_bfloat16* __restrict__ dstU,
                           __nv_bfloat16* __restrict__ dstW)
{
    int id = blockIdx.x * 256 + threadIdx.x;        // 7 * 262144 total
    int region = id >> 18;
    int off    = id & 262143;
    float v = sp.p[region][off];
    if (region < 4) { dstU[region * 262144 + off] = __float2bfloat16(v); }
    else            { dstW[(region - 4) * 262144 + off] = __float2bfloat16(v); }
}
__global__ void k_padW1(const float* __restrict__ w1, __nv_bfloat16* __restrict__ dst) {
    int i = blockIdx.x * blockDim.x + threadIdx.x;
    if (i < KPADE * HU) {
        int k = i / HU;
        int n = i - k * HU;
        float v = (k < EMBD) ? w1[k * HU + n] : 0.f;
        dst[i] = __float2bfloat16(v);
    }
}
__global__ void k_padEmb(const float* __restrict__ emb, __nv_bfloat16* __restrict__ dst) {
    long i = (long)blockIdx.x * blockDim.x + threadIdx.x;
    if (i < (long)VOCABN * KPADE) {
        int r = (int)(i / KPADE);
        int c = (int)(i - (long)r * KPADE);
        float v = (c < EMBD) ? emb[(long)r * EMBD + c] : 0.f;
        dst[i] = __float2bfloat16(v);
    }
}
__global__ void k_reset(int* __restrict__ flg) {
    int i = blockIdx.x * blockDim.x + threadIdx.x;
    if (i < 4 * 16 * 8) { flg[i] = 0; }
}
__global__ __launch_bounds__(256) void k_head(
    const __nv_bfloat16* __restrict__ sb, const float* __restrict__ wo,
    const float* __restrict__ bo, float* __restrict__ outp)
{
    const int m = blockIdx.x * 8 + (threadIdx.x >> 5);
    const int lane = threadIdx.x & 31;
    const __nv_bfloat16* hrow = sb + (long)m * ROWSTR + (SEQT - 1) * HU;
    float s = 0.f;
    for (int k = lane; k < HU; k += 32) {
        s = fmaf(__bfloat162float(hrow[k]), wo[k], s);
    }
    #pragma unroll
    for (int o = 16; o > 0; o >>= 1) {
        s += __shfl_xor_sync(0xFFFFFFFFu, s, o);
    }
    if (lane == 0) { outp[m] = 1.f / (1.f + expf(-(s + bo[0]))); }
}

// ---------------- launch ----------------
extern "C" void kernel_launch(void* const* d_in, const int* in_sizes, int n_in,
                              void* d_out, int out_size)
{
    (void)in_sizes; (void)n_in; (void)out_size;

    const int*   tokens = (const int*)  d_in[0];
    const float* emb    = (const float*)d_in[1];
    const float* wmat[4];
    const float* umat[4];
    const float* bvec[4];
    wmat[0] = (const float*)d_in[2];  umat[0] = (const float*)d_in[3];  bvec[0] = (const float*)d_in[4];
    wmat[1] = (const float*)d_in[5];  umat[1] = (const float*)d_in[6];  bvec[1] = (const float*)d_in[7];
    wmat[2] = (const float*)d_in[8];  umat[2] = (const float*)d_in[9];  bvec[2] = (const float*)d_in[10];
    wmat[3] = (const float*)d_in[11]; umat[3] = (const float*)d_in[12]; bvec[3] = (const float*)d_in[13];
    const float* wo = (const float*)d_in[14];
    const float* bo = (const float*)d_in[15];

    __nv_bfloat16* px = 0;
    __nv_bfloat16* psb = 0;
    __nv_bfloat16* pub = 0;
    __nv_bfloat16* pwb = 0;
    __nv_bfloat16* pw1 = 0;
    __nv_bfloat16* pemb = 0;
    int* pflg = 0;
    cudaGetSymbolAddress((void**)&px,   g_x);
    cudaGetSymbolAddress((void**)&psb,  g_sb);
    cudaGetSymbolAddress((void**)&pub,  g_Ub);
    cudaGetSymbolAddress((void**)&pwb,  g_Wb);
    cudaGetSymbolAddress((void**)&pw1,  g_W1b);
    cudaGetSymbolAddress((void**)&pemb, g_embb);
    cudaGetSymbolAddress((void**)&pflg, g_flags);

    cudaFuncSetAttribute(k_projx, cudaFuncAttributeMaxDynamicSharedMemorySize, SMEM_PROJ);
    cudaFuncSetAttribute(k_layer, cudaFuncAttributeMaxDynamicSharedMemorySize, SMEM_LAYER);

    // 0: fused weight conversion (U1..4, W2..4)
    SrcPtrs sp;
    sp.p[0] = umat[0]; sp.p[1] = umat[1]; sp.p[2] = umat[2]; sp.p[3] = umat[3];
    sp.p[4] = wmat[1]; sp.p[5] = wmat[2]; sp.p[6] = wmat[3];
    k_convertW<<<7 * 262144 / 256, 256>>>(sp, pub, pwb);
    // 1-2: padded conversions
    k_padW1<<<(KPADE * HU + 255) / 256, 256>>>(wmat[0], pw1);
    {
        long nemb = (long)VOCABN * KPADE;
        k_padEmb<<<(unsigned)((nemb + 255) / 256), 256>>>(emb, pemb);
    }
    // 3: flag reset (once; covers all 4 layers)
    k_reset<<<2, 256>>>(pflg);

    dim3 blk(256, 1, 1);
    dim3 gproj(8, 18, 1);      // 144 persistent blocks, single wave
    dim3 glayer(8, 16, 1);     // 128 persistent blocks

    const int nw = HU * HU;
    for (int l = 0; l < 4; l++) {
        if (l == 0) {
            k_projx<<<gproj, blk, SMEM_PROJ>>>(pemb, tokens, pw1, bvec[0], px, KPADE, 1);
        } else {
            k_projx<<<gproj, blk, SMEM_PROJ>>>(psb, (const int*)0,
                                               pwb + (size_t)(l - 1) * nw, bvec[l], px, HU, 0);
        }
        k_layer<<<glayer, blk, SMEM_LAYER>>>(pub + (size_t)l * nw, px, psb,
                                             pflg + l * 16 * 8);
    }

    k_head<<<BATCHN / 8, 256>>>(psb, wo, bo, (float*)d_out);
}